// round 1
// baseline (speedup 1.0000x reference)
#include <cuda_runtime.h>

#define Bn   4096
#define TWOB 8192
#define D    256
#define BM   64
#define BN   128
#define SPLIT_COLS 1024
#define NCT  (SPLIT_COLS / BN)   // 8 column tiles per split
#define NSPLIT 8

// Scratch (device globals — no allocation allowed)
__device__ __align__(16) float g_zn [TWOB * D];   // row-major normalized
__device__ __align__(16) float g_znT[D * TWOB];   // k-major (transposed) normalized
__device__ float g_denom[TWOB];
__device__ float g_loss;

typedef unsigned long long u64;

__device__ __forceinline__ u64 pk2(float lo, float hi) {
    u64 r; asm("mov.b64 %0, {%1, %2};" : "=l"(r) : "f"(lo), "f"(hi)); return r;
}
__device__ __forceinline__ void upk2(u64 v, float& lo, float& hi) {
    asm("mov.b64 {%0, %1}, %2;" : "=f"(lo), "=f"(hi) : "l"(v));
}
__device__ __forceinline__ void ffma2(u64& d, u64 a, u64 b) {
    asm("fma.rn.f32x2 %0, %1, %2, %0;" : "+l"(d) : "l"(a), "l"(b));
}

// ---------------------------------------------------------------------------
// Kernel 1: normalize rows of [z1;z2], write both row-major and transposed
// copies; zero the accumulators. One warp per row.
// ---------------------------------------------------------------------------
__global__ void k_prep(const float* __restrict__ z1, const float* __restrict__ z2) {
    int gtid = blockIdx.x * blockDim.x + threadIdx.x;
    int row  = gtid >> 5;
    int lane = gtid & 31;
    if (row >= TWOB) return;
    const float* src = (row < Bn) ? (z1 + row * D) : (z2 + (row - Bn) * D);
    float v[8];
    float ss = 0.f;
#pragma unroll
    for (int j = 0; j < 8; j++) { v[j] = src[lane + 32 * j]; ss += v[j] * v[j]; }
#pragma unroll
    for (int o = 16; o > 0; o >>= 1) ss += __shfl_xor_sync(0xffffffffu, ss, o);
    float inv = 1.f / fmaxf(sqrtf(ss), 1e-8f);
#pragma unroll
    for (int j = 0; j < 8; j++) {
        float nv = v[j] * inv;
        g_zn [row * D + lane + 32 * j] = nv;
        g_znT[(lane + 32 * j) * TWOB + row] = nv;
    }
    if (gtid < TWOB) g_denom[gtid] = 0.f;
    if (gtid == 0)   g_loss = 0.f;
}

// ---------------------------------------------------------------------------
// Kernel 2: fused sim-GEMM + exp-row-sum (denominator), diagonal masked.
// Block: 64 rows x 1024 cols (looped as 8 tiles of 128 cols).
// Thread micro-tile: 4 rows x 8 cols, accumulated in packed f32x2.
// ---------------------------------------------------------------------------
__global__ __launch_bounds__(256, 2) void k_sim() {
    extern __shared__ float smem[];
    float* As  = smem;                  // [256][64]   (k-major) = 64 KB
    float* Bs  = smem + 256 * BM;       // [64][128]   (k-major) = 32 KB
    float* red = Bs + 64 * BN;          // [64][16]               = 4 KB

    const int tid = threadIdx.x;
    const int tx  = tid & 15;           // 16 col-groups of 8
    const int ty  = tid >> 4;           // 16 row-groups of 4
    const int R0  = blockIdx.x * BM;
    const int CB  = blockIdx.y * SPLIT_COLS;
    const int arow = ty * 4;

    // Load full A row-block (64 rows x all 256 k) — conflict-free copy from g_znT
#pragma unroll
    for (int it = 0; it < 16; ++it) {
        int idx = it * 256 + tid;
        int k = idx >> 4, mq = (idx & 15) << 2;
        *(float4*)&As[k * BM + mq] = *(const float4*)&g_znT[k * TWOB + R0 + mq];
    }

    float rs[4] = {0.f, 0.f, 0.f, 0.f};

    for (int ct = 0; ct < NCT; ++ct) {
        const int C0 = CB + ct * BN;
        u64 acc[4][4];
#pragma unroll
        for (int i = 0; i < 4; i++)
#pragma unroll
            for (int p = 0; p < 4; p++) acc[i][p] = 0ull;

        for (int kt = 0; kt < 4; ++kt) {
            __syncthreads();   // previous Bs fully consumed
#pragma unroll
            for (int it = 0; it < 8; ++it) {
                int idx = it * 256 + tid;
                int k = idx >> 5, nq = (idx & 31) << 2;
                *(float4*)&Bs[k * BN + nq] =
                    *(const float4*)&g_znT[(kt * 64 + k) * TWOB + C0 + nq];
            }
            __syncthreads();

            const float* Ak = As + (kt * 64) * BM;
#pragma unroll 16
            for (int k = 0; k < 64; ++k) {
                float4 av = *(const float4*)&Ak[k * BM + arow];
                u64 aa0 = pk2(av.x, av.x);
                u64 aa1 = pk2(av.y, av.y);
                u64 aa2 = pk2(av.z, av.z);
                u64 aa3 = pk2(av.w, av.w);
                unsigned ba = (unsigned)__cvta_generic_to_shared(&Bs[k * BN + tx * 8]);
                u64 b0, b1, b2, b3;
                asm volatile("ld.shared.v2.u64 {%0,%1}, [%2];"
                             : "=l"(b0), "=l"(b1) : "r"(ba));
                asm volatile("ld.shared.v2.u64 {%0,%1}, [%2];"
                             : "=l"(b2), "=l"(b3) : "r"(ba + 16));
                ffma2(acc[0][0], aa0, b0); ffma2(acc[0][1], aa0, b1);
                ffma2(acc[0][2], aa0, b2); ffma2(acc[0][3], aa0, b3);
                ffma2(acc[1][0], aa1, b0); ffma2(acc[1][1], aa1, b1);
                ffma2(acc[1][2], aa1, b2); ffma2(acc[1][3], aa1, b3);
                ffma2(acc[2][0], aa2, b0); ffma2(acc[2][1], aa2, b1);
                ffma2(acc[2][2], aa2, b2); ffma2(acc[2][3], aa2, b3);
                ffma2(acc[3][0], aa3, b0); ffma2(acc[3][1], aa3, b1);
                ffma2(acc[3][2], aa3, b2); ffma2(acc[3][3], aa3, b3);
            }
        }

        // Epilogue: exp(sim/T), T=0.5 -> exp(2*sim); skip the self-diagonal.
#pragma unroll
        for (int i = 0; i < 4; i++) {
            int grow = R0 + arow + i;
#pragma unroll
            for (int p = 0; p < 4; p++) {
                float lo, hi; upk2(acc[i][p], lo, hi);
                int gcol = C0 + tx * 8 + p * 2;
                if (grow != gcol)     rs[i] += __expf(2.f * lo);
                if (grow != gcol + 1) rs[i] += __expf(2.f * hi);
            }
        }
    }

    // Reduce 16 tx-partials per row, accumulate into global denominator.
#pragma unroll
    for (int i = 0; i < 4; i++) red[(arow + i) * 16 + tx] = rs[i];
    __syncthreads();
    if (tid < 64) {
        float s = 0.f;
#pragma unroll
        for (int t = 0; t < 16; t++) s += red[tid * 16 + t];
        atomicAdd(&g_denom[R0 + tid], s);
    }
}

// ---------------------------------------------------------------------------
// Kernel 3: positives (diagonal offsets ±B) + per-row loss, reduce to scalar.
// One warp per row. loss_i = log(denom_i) - log(pos_i).
// ---------------------------------------------------------------------------
__global__ void k_loss() {
    int gtid = blockIdx.x * blockDim.x + threadIdx.x;
    int row  = gtid >> 5;
    int lane = gtid & 31;
    if (row >= TWOB) return;
    int partner = (row < Bn) ? row + Bn : row - Bn;
    const float* a = g_zn + row * D;
    const float* b = g_zn + partner * D;
    float dot = 0.f;
#pragma unroll
    for (int j = 0; j < 8; j++) dot += a[lane + 32 * j] * b[lane + 32 * j];
#pragma unroll
    for (int o = 16; o > 0; o >>= 1) dot += __shfl_xor_sync(0xffffffffu, dot, o);
    if (lane == 0) {
        float l = __logf(g_denom[row]) - __logf(dot);
        atomicAdd(&g_loss, l);
    }
}

__global__ void k_final(float* out) {
    out[0] = g_loss * (1.f / (float)TWOB);
}

// ---------------------------------------------------------------------------
extern "C" void kernel_launch(void* const* d_in, const int* in_sizes, int n_in,
                              void* d_out, int out_size) {
    const float* z1 = (const float*)d_in[0];
    const float* z2 = (const float*)d_in[1];
    float* out = (float*)d_out;

    const int smem_bytes = 256 * BM * 4 + 64 * BN * 4 + 64 * 16 * 4;  // 102400
    cudaFuncSetAttribute(k_sim, cudaFuncAttributeMaxDynamicSharedMemorySize, smem_bytes);

    k_prep<<<TWOB * 32 / 256, 256>>>(z1, z2);
    k_sim<<<dim3(TWOB / BM, NSPLIT), 256, smem_bytes>>>();
    k_loss<<<TWOB * 32 / 256, 256>>>();
    k_final<<<1, 1>>>(out);
}

// round 3
// speedup vs baseline: 6.1215x; 6.1215x over previous
#include <cuda_runtime.h>
#include <cuda_bf16.h>
#include <cstdint>

#define Bn    4096
#define TWOB  8192
#define D     256
#define BM    128
#define BN    256

// Scratch (device globals — no allocation allowed)
__device__ __align__(16) float          g_zn  [TWOB * D];   // fp32 normalized (exact positives)
__device__ __align__(16) __nv_bfloat16  g_znbf[TWOB * D];   // bf16 normalized (GEMM operand)
__device__ float g_denom[TWOB];
__device__ float g_loss;

// ---------------------------------------------------------------------------
__device__ __forceinline__ uint32_t smem_u32(const void* p) {
    uint32_t a;
    asm("{ .reg .u64 t; cvta.to.shared.u64 t, %1; cvt.u32.u64 %0, t; }" : "=r"(a) : "l"(p));
    return a;
}

__device__ __forceinline__ void ldsm_x4(uint32_t& r0, uint32_t& r1, uint32_t& r2, uint32_t& r3,
                                        uint32_t addr) {
    asm volatile("ldmatrix.sync.aligned.m8n8.x4.shared.b16 {%0,%1,%2,%3}, [%4];"
                 : "=r"(r0), "=r"(r1), "=r"(r2), "=r"(r3) : "r"(addr));
}

__device__ __forceinline__ void mma16816(float* c, const uint32_t* a, uint32_t b0, uint32_t b1) {
    asm volatile(
        "mma.sync.aligned.m16n8k16.row.col.f32.bf16.bf16.f32 "
        "{%0,%1,%2,%3}, {%4,%5,%6,%7}, {%8,%9}, {%0,%1,%2,%3};"
        : "+f"(c[0]), "+f"(c[1]), "+f"(c[2]), "+f"(c[3])
        : "r"(a[0]), "r"(a[1]), "r"(a[2]), "r"(a[3]), "r"(b0), "r"(b1));
}

// ---------------------------------------------------------------------------
// Kernel 1: normalize rows of [z1;z2]; emit fp32 + bf16 copies; zero accums.
// One warp per row.
// ---------------------------------------------------------------------------
__global__ void k_prep(const float* __restrict__ z1, const float* __restrict__ z2) {
    int gtid = blockIdx.x * blockDim.x + threadIdx.x;
    int row  = gtid >> 5;
    int lane = gtid & 31;
    if (row >= TWOB) return;
    const float* src = (row < Bn) ? (z1 + row * D) : (z2 + (row - Bn) * D);
    float v[8];
    float ss = 0.f;
#pragma unroll
    for (int j = 0; j < 8; j++) { v[j] = src[lane + 32 * j]; ss += v[j] * v[j]; }
#pragma unroll
    for (int o = 16; o > 0; o >>= 1) ss += __shfl_xor_sync(0xffffffffu, ss, o);
    float inv = 1.f / fmaxf(sqrtf(ss), 1e-8f);
#pragma unroll
    for (int j = 0; j < 8; j++) {
        float nv = v[j] * inv;
        g_zn  [row * D + lane + 32 * j] = nv;
        g_znbf[row * D + lane + 32 * j] = __float2bfloat16(nv);
    }
    if (gtid < TWOB) g_denom[gtid] = 0.f;
    if (gtid == 0)   g_loss = 0.f;
}

// ---------------------------------------------------------------------------
// Stage a [nrows x 256] bf16 tile into SMEM with XOR-8 swizzle (16B chunks).
// Row = 512 B = 32 chunks; chunk c stored at (c ^ (row&7)).
// ---------------------------------------------------------------------------
__device__ __forceinline__ void stage_tile(uint32_t sbase, const uint4* __restrict__ src,
                                           int row0, int nrows, int tid) {
    for (int i = tid; i < nrows * 32; i += 256) {
        int r = i >> 5, c = i & 31;
        uint4 v = __ldg(&src[(size_t)(row0 + r) * 32 + c]);
        uint32_t dst = sbase + (uint32_t)r * 512u + (uint32_t)((c ^ (r & 7)) << 4);
        asm volatile("st.shared.v4.b32 [%0], {%1,%2,%3,%4};"
                     :: "r"(dst), "r"(v.x), "r"(v.y), "r"(v.z), "r"(v.w));
    }
}

// ---------------------------------------------------------------------------
// Kernel 2: bf16 mma.sync sim-GEMM fused with exp row-sum (diagonal masked).
// CTA tile 128x256, full K=256 SMEM-resident. 8 warps: 4 along M x 2 along N;
// warp tile 32x128 (2 m16-tiles x 16 n8-tiles).
// ---------------------------------------------------------------------------
__global__ __launch_bounds__(256, 1) void k_sim_mma() {
    extern __shared__ char smem[];
    const uint32_t sbA = smem_u32(smem);            // 128*512 = 64 KB
    const uint32_t sbB = sbA + 128 * 512;           // 256*512 = 128 KB

    const int tid  = threadIdx.x;
    const int lane = tid & 31;
    const int wid  = tid >> 5;
    const int wm   = wid & 3;        // 4 warps along M
    const int wn   = wid >> 2;       // 2 warps along N
    const int R0   = blockIdx.x * BM;
    const int C0   = blockIdx.y * BN;

    const uint4* zn4 = (const uint4*)g_znbf;
    stage_tile(sbA, zn4, R0, 128, tid);
    stage_tile(sbB, zn4, C0, 256, tid);
    __syncthreads();

    float acc[2][16][4];
#pragma unroll
    for (int mi = 0; mi < 2; mi++)
#pragma unroll
        for (int nj = 0; nj < 16; nj++)
#pragma unroll
            for (int q = 0; q < 4; q++) acc[mi][nj][q] = 0.f;

    const int lrow = lane & 15;
    const int lsel = lane >> 4;

#pragma unroll 4
    for (int k16 = 0; k16 < 16; ++k16) {
        const int ch = k16 * 2 + lsel;
        uint32_t a[2][4];
#pragma unroll
        for (int mi = 0; mi < 2; mi++) {
            int r = wm * 32 + mi * 16 + lrow;
            uint32_t ad = sbA + (uint32_t)r * 512u + (uint32_t)(((ch ^ (r & 7)) & 31) << 4);
            ldsm_x4(a[mi][0], a[mi][1], a[mi][2], a[mi][3], ad);
        }
        uint32_t b[8][4];
#pragma unroll
        for (int nj = 0; nj < 8; nj++) {
            int r = wn * 128 + nj * 16 + lrow;
            uint32_t bd = sbB + (uint32_t)r * 512u + (uint32_t)(((ch ^ (r & 7)) & 31) << 4);
            ldsm_x4(b[nj][0], b[nj][1], b[nj][2], b[nj][3], bd);
        }
#pragma unroll
        for (int mi = 0; mi < 2; mi++)
#pragma unroll
            for (int nj = 0; nj < 8; nj++) {
                mma16816(acc[mi][2 * nj + 0], a[mi], b[nj][0], b[nj][2]);
                mma16816(acc[mi][2 * nj + 1], a[mi], b[nj][1], b[nj][3]);
            }
    }

    // Epilogue: exp(2*sim), skip self-diagonal, per-row sums.
    // Fragment layout: c0,c1 -> row qrow, cols qcol+{0,1}; c2,c3 -> row qrow+8.
    const int qrow = lane >> 2;
    const int qcol = (lane & 3) * 2;
    float rs[4] = {0.f, 0.f, 0.f, 0.f};
#pragma unroll
    for (int mi = 0; mi < 2; mi++) {
        const int r0 = R0 + wm * 32 + mi * 16 + qrow;
        const int r1 = r0 + 8;
#pragma unroll
        for (int nj = 0; nj < 16; nj++) {
            const int c = C0 + wn * 128 + nj * 8 + qcol;
            const float* f = acc[mi][nj];
            if (c     != r0) rs[2 * mi]     += __expf(2.f * f[0]);
            if (c + 1 != r0) rs[2 * mi]     += __expf(2.f * f[1]);
            if (c     != r1) rs[2 * mi + 1] += __expf(2.f * f[2]);
            if (c + 1 != r1) rs[2 * mi + 1] += __expf(2.f * f[3]);
        }
    }
#pragma unroll
    for (int s = 0; s < 4; s++) {
        rs[s] += __shfl_xor_sync(0xffffffffu, rs[s], 1);
        rs[s] += __shfl_xor_sync(0xffffffffu, rs[s], 2);
    }
    if ((lane & 3) == 0) {
        atomicAdd(&g_denom[R0 + wm * 32 +  0 + qrow], rs[0]);
        atomicAdd(&g_denom[R0 + wm * 32 +  8 + qrow], rs[1]);
        atomicAdd(&g_denom[R0 + wm * 32 + 16 + qrow], rs[2]);
        atomicAdd(&g_denom[R0 + wm * 32 + 24 + qrow], rs[3]);
    }
}

// ---------------------------------------------------------------------------
// Kernel 3: positives (exact fp32) + per-row loss, reduce to scalar.
// ---------------------------------------------------------------------------
__global__ void k_loss() {
    int gtid = blockIdx.x * blockDim.x + threadIdx.x;
    int row  = gtid >> 5;
    int lane = gtid & 31;
    if (row >= TWOB) return;
    int partner = (row < Bn) ? row + Bn : row - Bn;
    const float* a = g_zn + row * D;
    const float* b = g_zn + partner * D;
    float dot = 0.f;
#pragma unroll
    for (int j = 0; j < 8; j++) dot += a[lane + 32 * j] * b[lane + 32 * j];
#pragma unroll
    for (int o = 16; o > 0; o >>= 1) dot += __shfl_xor_sync(0xffffffffu, dot, o);
    if (lane == 0) {
        float l = __logf(g_denom[row]) - __logf(dot);
        atomicAdd(&g_loss, l);
    }
}

__global__ void k_final(float* out) {
    out[0] = g_loss * (1.f / (float)TWOB);
}

// ---------------------------------------------------------------------------
extern "C" void kernel_launch(void* const* d_in, const int* in_sizes, int n_in,
                              void* d_out, int out_size) {
    const float* z1 = (const float*)d_in[0];
    const float* z2 = (const float*)d_in[1];
    float* out = (float*)d_out;

    const int smem_bytes = (128 + 256) * 512;   // 196608
    cudaFuncSetAttribute(k_sim_mma, cudaFuncAttributeMaxDynamicSharedMemorySize, smem_bytes);

    k_prep<<<TWOB * 32 / 256, 256>>>(z1, z2);
    k_sim_mma<<<dim3(TWOB / BM, TWOB / BN), 256, smem_bytes>>>();
    k_loss<<<TWOB * 32 / 256, 256>>>();
    k_final<<<1, 1>>>(out);
}

// round 4
// speedup vs baseline: 10.7748x; 1.7602x over previous
#include <cuda_runtime.h>
#include <cuda_bf16.h>
#include <cstdint>

#define Bn    4096
#define TWOB  8192
#define D     256
#define BT    128               // tile edge
#define NT    (TWOB / BT)       // 64 tile bands
#define NTILES (NT * (NT + 1) / 2)   // 2080 triangular tiles

// Scratch (device globals — no allocation allowed)
__device__ __align__(16) float          g_zn  [TWOB * D];   // fp32 normalized (exact positives)
__device__ __align__(16) __nv_bfloat16  g_znbf[TWOB * D];   // bf16 normalized (GEMM operand)
__device__ float g_denom[TWOB];
__device__ float g_loss;
__device__ unsigned int g_count;

// ---------------------------------------------------------------------------
__device__ __forceinline__ uint32_t smem_u32(const void* p) {
    uint32_t a;
    asm("{ .reg .u64 t; cvta.to.shared.u64 t, %1; cvt.u32.u64 %0, t; }" : "=r"(a) : "l"(p));
    return a;
}
__device__ __forceinline__ void ldsm_x4(uint32_t& r0, uint32_t& r1, uint32_t& r2, uint32_t& r3,
                                        uint32_t addr) {
    asm volatile("ldmatrix.sync.aligned.m8n8.x4.shared.b16 {%0,%1,%2,%3}, [%4];"
                 : "=r"(r0), "=r"(r1), "=r"(r2), "=r"(r3) : "r"(addr));
}
__device__ __forceinline__ void mma16816(float* c, const uint32_t* a, uint32_t b0, uint32_t b1) {
    asm volatile(
        "mma.sync.aligned.m16n8k16.row.col.f32.bf16.bf16.f32 "
        "{%0,%1,%2,%3}, {%4,%5,%6,%7}, {%8,%9}, {%0,%1,%2,%3};"
        : "+f"(c[0]), "+f"(c[1]), "+f"(c[2]), "+f"(c[3])
        : "r"(a[0]), "r"(a[1]), "r"(a[2]), "r"(a[3]), "r"(b0), "r"(b1));
}
#define CP_COMMIT() asm volatile("cp.async.commit_group;" ::: "memory")
#define CP_WAIT0()  asm volatile("cp.async.wait_group 0;" ::: "memory")

// Async-stage one 128x256 bf16 tile (row r, 16B chunk c -> r*512 + ((c^(r&7))<<4))
__device__ __forceinline__ void stage_async(uint32_t sbase, const uint4* __restrict__ src,
                                            int row0, int tid) {
#pragma unroll
    for (int it = 0; it < 16; ++it) {
        int i = it * 256 + tid;
        int r = i >> 5, c = i & 31;
        const uint4* g = src + (size_t)(row0 + r) * 32 + c;
        uint32_t dst = sbase + (uint32_t)r * 512u + (uint32_t)((c ^ (r & 7)) << 4);
        asm volatile("cp.async.cg.shared.global [%0], [%1], 16;" :: "r"(dst), "l"(g));
    }
}

__device__ __forceinline__ void decode_tile(int t, int& I, int& J) {
    int i = 0, s = 0;
    while (s + (NT - i) <= t) { s += NT - i; ++i; }
    I = i; J = i + (t - s);
}

// ---------------------------------------------------------------------------
// Kernel 1: normalize rows; emit fp32 + bf16 copies; zero accumulators.
// ---------------------------------------------------------------------------
__global__ void k_prep(const float* __restrict__ z1, const float* __restrict__ z2) {
    int gtid = blockIdx.x * blockDim.x + threadIdx.x;
    int row  = gtid >> 5;
    int lane = gtid & 31;
    if (row >= TWOB) return;
    const float* src = (row < Bn) ? (z1 + row * D) : (z2 + (row - Bn) * D);
    float v[8];
    float ss = 0.f;
#pragma unroll
    for (int j = 0; j < 8; j++) { v[j] = src[lane + 32 * j]; ss += v[j] * v[j]; }
#pragma unroll
    for (int o = 16; o > 0; o >>= 1) ss += __shfl_xor_sync(0xffffffffu, ss, o);
    float inv = 1.f / fmaxf(sqrtf(ss), 1e-8f);
#pragma unroll
    for (int j = 0; j < 8; j++) {
        float nv = v[j] * inv;
        g_zn  [row * D + lane + 32 * j] = nv;
        g_znbf[row * D + lane + 32 * j] = __float2bfloat16(nv);
    }
    if (gtid < TWOB) g_denom[gtid] = 0.f;
    if (gtid == 0)   { g_loss = 0.f; g_count = 0u; }
}

// ---------------------------------------------------------------------------
// Kernel 2: symmetric bf16 sim-GEMM + exp sums over triangular tiles.
// Each CTA owns a contiguous tile range (A-band reuse); B double-buffered
// via cp.async. 256 threads; warp tile 32x64.
// ---------------------------------------------------------------------------
__global__ __launch_bounds__(256, 1) void k_sim_mma() {
    extern __shared__ char smem[];
    const uint32_t sbA  = smem_u32(smem);        // 64 KB
    const uint32_t sbB0 = sbA + 65536;           // 64 KB
    const uint32_t sbB1 = sbB0 + 65536;          // 64 KB

    const int t0 = (int)(((long long)NTILES * blockIdx.x) / gridDim.x);
    const int t1 = (int)(((long long)NTILES * (blockIdx.x + 1)) / gridDim.x);

    const int tid  = threadIdx.x;
    const int lane = tid & 31;
    const int wid  = tid >> 5;
    const int wm   = wid & 3;       // 4 warps along M (32 rows each)
    const int wn   = wid >> 2;      // 2 warps along N (64 cols each)
    const int lrow = lane & 15;
    const int lsel = lane >> 4;
    const int qrow = lane >> 2;
    const int qcol = (lane & 3) * 2;

    const uint4* zn4 = (const uint4*)g_znbf;
    int curI = -1;

    for (int t = t0; t < t1; ++t) {
        int I, J; decode_tile(t, I, J);
        const uint32_t sbB  = ((t - t0) & 1) ? sbB1 : sbB0;
        const uint32_t sbBn = ((t - t0) & 1) ? sbB0 : sbB1;

        if (I != curI) {   // band change: stage A and this B synchronously
            stage_async(sbA, zn4, I * BT, tid);
            stage_async(sbB, zn4, J * BT, tid);
            CP_COMMIT(); CP_WAIT0();
            __syncthreads();
            curI = I;
        }
        // prefetch next B while computing, if staying in this band
        if (t + 1 < t1) {
            int In, Jn; decode_tile(t + 1, In, Jn);
            if (In == curI) { stage_async(sbBn, zn4, Jn * BT, tid); CP_COMMIT(); }
        }

        // ---- compute 128x128 tile ----
        float acc[2][8][4];
#pragma unroll
        for (int mi = 0; mi < 2; mi++)
#pragma unroll
            for (int nj = 0; nj < 8; nj++)
#pragma unroll
                for (int q = 0; q < 4; q++) acc[mi][nj][q] = 0.f;

#pragma unroll 4
        for (int k16 = 0; k16 < 16; ++k16) {
            const int ch = k16 * 2 + lsel;
            uint32_t a[2][4];
#pragma unroll
            for (int mi = 0; mi < 2; mi++) {
                int r = wm * 32 + mi * 16 + lrow;
                uint32_t ad = sbA + (uint32_t)r * 512u + (uint32_t)(((ch ^ (r & 7)) & 31) << 4);
                ldsm_x4(a[mi][0], a[mi][1], a[mi][2], a[mi][3], ad);
            }
            uint32_t b[4][4];
#pragma unroll
            for (int nb = 0; nb < 4; nb++) {
                int r = wn * 64 + nb * 16 + lrow;
                uint32_t bd = sbB + (uint32_t)r * 512u + (uint32_t)(((ch ^ (r & 7)) & 31) << 4);
                ldsm_x4(b[nb][0], b[nb][1], b[nb][2], b[nb][3], bd);
            }
#pragma unroll
            for (int mi = 0; mi < 2; mi++)
#pragma unroll
                for (int nb = 0; nb < 4; nb++) {
                    mma16816(acc[mi][2 * nb + 0], a[mi], b[nb][0], b[nb][2]);
                    mma16816(acc[mi][2 * nb + 1], a[mi], b[nb][1], b[nb][3]);
                }
        }

        // ---- epilogue: exp(2*sim); row sums always, col sums if I != J ----
        const bool diag = (I == J);
        float rs[4] = {0.f, 0.f, 0.f, 0.f};
        float cs[8][2];
#pragma unroll
        for (int nj = 0; nj < 8; nj++) { cs[nj][0] = 0.f; cs[nj][1] = 0.f; }

#pragma unroll
        for (int mi = 0; mi < 2; mi++) {
            const int lr0 = wm * 32 + mi * 16 + qrow;
            const int lr1 = lr0 + 8;
#pragma unroll
            for (int nj = 0; nj < 8; nj++) {
                const int lc = wn * 64 + nj * 8 + qcol;
                const float* f = acc[mi][nj];
                float e0 = __expf(2.f * f[0]);
                float e1 = __expf(2.f * f[1]);
                float e2 = __expf(2.f * f[2]);
                float e3 = __expf(2.f * f[3]);
                if (diag) {
                    if (lc     == lr0) e0 = 0.f;
                    if (lc + 1 == lr0) e1 = 0.f;
                    if (lc     == lr1) e2 = 0.f;
                    if (lc + 1 == lr1) e3 = 0.f;
                }
                rs[2 * mi]     += e0 + e1;
                rs[2 * mi + 1] += e2 + e3;
                cs[nj][0] += e0 + e2;
                cs[nj][1] += e1 + e3;
            }
        }

        // row sums: reduce across the 4 qcol lanes
#pragma unroll
        for (int s = 0; s < 4; s++) {
            rs[s] += __shfl_xor_sync(0xffffffffu, rs[s], 1);
            rs[s] += __shfl_xor_sync(0xffffffffu, rs[s], 2);
        }
        if ((lane & 3) == 0) {
            int rbase = I * BT + wm * 32 + qrow;
            atomicAdd(&g_denom[rbase],      rs[0]);
            atomicAdd(&g_denom[rbase + 8],  rs[1]);
            atomicAdd(&g_denom[rbase + 16], rs[2]);
            atomicAdd(&g_denom[rbase + 24], rs[3]);
        }
        // col sums (symmetric contribution): reduce across the 8 qrow lanes
        if (!diag) {
#pragma unroll
            for (int nj = 0; nj < 8; nj++)
#pragma unroll
                for (int c = 0; c < 2; c++) {
                    cs[nj][c] += __shfl_xor_sync(0xffffffffu, cs[nj][c], 4);
                    cs[nj][c] += __shfl_xor_sync(0xffffffffu, cs[nj][c], 8);
                    cs[nj][c] += __shfl_xor_sync(0xffffffffu, cs[nj][c], 16);
                }
            if (lane < 4) {
                int cbase = J * BT + wn * 64 + lane * 2;
#pragma unroll
                for (int nj = 0; nj < 8; nj++) {
                    atomicAdd(&g_denom[cbase + nj * 8],     cs[nj][0]);
                    atomicAdd(&g_denom[cbase + nj * 8 + 1], cs[nj][1]);
                }
            }
        }

        CP_WAIT0();        // next B landed
        __syncthreads();   // all warps done with current buffers
    }
}

// ---------------------------------------------------------------------------
// Kernel 3: positives (exact fp32) + per-row loss; last block writes output.
// ---------------------------------------------------------------------------
__global__ void k_loss(float* __restrict__ out) {
    int gtid = blockIdx.x * blockDim.x + threadIdx.x;
    int row  = gtid >> 5;
    int lane = gtid & 31;
    int partner = (row < Bn) ? row + Bn : row - Bn;
    const float* a = g_zn + row * D;
    const float* b = g_zn + partner * D;
    float dot = 0.f;
#pragma unroll
    for (int j = 0; j < 8; j++) dot += a[lane + 32 * j] * b[lane + 32 * j];
#pragma unroll
    for (int o = 16; o > 0; o >>= 1) dot += __shfl_xor_sync(0xffffffffu, dot, o);
    if (lane == 0) {
        float l = __logf(g_denom[row]) - __logf(dot);
        atomicAdd(&g_loss, l);
    }
    __syncthreads();
    if (threadIdx.x == 0) {
        __threadfence();
        unsigned int done = atomicAdd(&g_count, 1u);
        if (done == gridDim.x - 1)
            out[0] = g_loss * (1.f / (float)TWOB);
    }
}

// ---------------------------------------------------------------------------
extern "C" void kernel_launch(void* const* d_in, const int* in_sizes, int n_in,
                              void* d_out, int out_size) {
    const float* z1 = (const float*)d_in[0];
    const float* z2 = (const float*)d_in[1];
    float* out = (float*)d_out;

    int nsm = 148;
    cudaDeviceGetAttribute(&nsm, cudaDevAttrMultiProcessorCount, 0);

    const int smem_bytes = 3 * 65536;   // 192 KB
    cudaFuncSetAttribute(k_sim_mma, cudaFuncAttributeMaxDynamicSharedMemorySize, smem_bytes);

    k_prep<<<TWOB * 32 / 256, 256>>>(z1, z2);
    k_sim_mma<<<nsm, 256, smem_bytes>>>();
    k_loss<<<TWOB * 32 / 256, 256>>>(out);
}

// round 5
// speedup vs baseline: 12.4351x; 1.1541x over previous
#include <cuda_runtime.h>
#include <cuda_bf16.h>
#include <cstdint>

#define Bn    4096
#define TWOB  8192
#define D     256
#define BT    128               // tile edge
#define NT    (TWOB / BT)       // 64 tile bands
#define NTILES (NT * (NT + 1) / 2)   // 2080 triangular tiles

// Scratch (device globals — no allocation allowed)
__device__ __align__(16) __nv_bfloat16  g_znbf[TWOB * D];   // bf16 normalized (GEMM operand)
__device__ float g_pos[Bn];      // exact fp32 positive cosine sims
__device__ float g_denom[TWOB];
__device__ float g_loss;
__device__ unsigned int g_count;

// ---------------------------------------------------------------------------
__device__ __forceinline__ uint32_t smem_u32(const void* p) {
    uint32_t a;
    asm("{ .reg .u64 t; cvta.to.shared.u64 t, %1; cvt.u32.u64 %0, t; }" : "=r"(a) : "l"(p));
    return a;
}
__device__ __forceinline__ void ldsm_x4(uint32_t& r0, uint32_t& r1, uint32_t& r2, uint32_t& r3,
                                        uint32_t addr) {
    asm volatile("ldmatrix.sync.aligned.m8n8.x4.shared.b16 {%0,%1,%2,%3}, [%4];"
                 : "=r"(r0), "=r"(r1), "=r"(r2), "=r"(r3) : "r"(addr));
}
__device__ __forceinline__ void mma16816(float* c, const uint32_t* a, uint32_t b0, uint32_t b1) {
    asm volatile(
        "mma.sync.aligned.m16n8k16.row.col.f32.bf16.bf16.f32 "
        "{%0,%1,%2,%3}, {%4,%5,%6,%7}, {%8,%9}, {%0,%1,%2,%3};"
        : "+f"(c[0]), "+f"(c[1]), "+f"(c[2]), "+f"(c[3])
        : "r"(a[0]), "r"(a[1]), "r"(a[2]), "r"(a[3]), "r"(b0), "r"(b1));
}
#define CP_COMMIT() asm volatile("cp.async.commit_group;" ::: "memory")
#define CP_WAIT0()  asm volatile("cp.async.wait_group 0;" ::: "memory")

// Async-stage one 128x256 bf16 tile (row r, 16B chunk c -> r*512 + ((c^(r&7))<<4))
__device__ __forceinline__ void stage_async(uint32_t sbase, const uint4* __restrict__ src,
                                            int row0, int tid) {
#pragma unroll
    for (int it = 0; it < 16; ++it) {
        int i = it * 256 + tid;
        int r = i >> 5, c = i & 31;
        const uint4* g = src + (size_t)(row0 + r) * 32 + c;
        uint32_t dst = sbase + (uint32_t)r * 512u + (uint32_t)((c ^ (r & 7)) << 4);
        asm volatile("cp.async.cg.shared.global [%0], [%1], 16;" :: "r"(dst), "l"(g));
    }
}

__device__ __forceinline__ void decode_tile(int t, int& I, int& J) {
    int i = 0, s = 0;
    while (s + (NT - i) <= t) { s += NT - i; ++i; }
    I = i; J = i + (t - s);
}

// ---------------------------------------------------------------------------
// Kernel 1: normalize row pairs (z1_i, z2_i); emit bf16 rows i and i+Bn,
// exact fp32 positive sims; zero accumulators. One warp per pair, float4 IO.
// ---------------------------------------------------------------------------
__global__ void k_prep(const float* __restrict__ z1, const float* __restrict__ z2) {
    int gtid = blockIdx.x * blockDim.x + threadIdx.x;
    if (gtid < TWOB) g_denom[gtid] = 0.f;
    if (gtid == 0)   { g_loss = 0.f; g_count = 0u; }
    int pair = gtid >> 5;
    int lane = gtid & 31;
    if (pair >= Bn) return;
    const float4* a4 = (const float4*)(z1 + (size_t)pair * D);
    const float4* b4 = (const float4*)(z2 + (size_t)pair * D);
    float4 va[2], vb[2];
    float ss1 = 0.f, ss2 = 0.f, dot = 0.f;
#pragma unroll
    for (int j = 0; j < 2; j++) {
        va[j] = a4[lane + 32 * j];
        vb[j] = b4[lane + 32 * j];
        ss1 += va[j].x * va[j].x + va[j].y * va[j].y + va[j].z * va[j].z + va[j].w * va[j].w;
        ss2 += vb[j].x * vb[j].x + vb[j].y * vb[j].y + vb[j].z * vb[j].z + vb[j].w * vb[j].w;
        dot += va[j].x * vb[j].x + va[j].y * vb[j].y + va[j].z * vb[j].z + va[j].w * vb[j].w;
    }
#pragma unroll
    for (int o = 16; o > 0; o >>= 1) {
        ss1 += __shfl_xor_sync(0xffffffffu, ss1, o);
        ss2 += __shfl_xor_sync(0xffffffffu, ss2, o);
        dot += __shfl_xor_sync(0xffffffffu, dot, o);
    }
    float inv1 = 1.f / fmaxf(sqrtf(ss1), 1e-8f);
    float inv2 = 1.f / fmaxf(sqrtf(ss2), 1e-8f);

    __nv_bfloat162* r1 = (__nv_bfloat162*)(g_znbf + (size_t)pair * D);
    __nv_bfloat162* r2 = (__nv_bfloat162*)(g_znbf + (size_t)(pair + Bn) * D);
#pragma unroll
    for (int j = 0; j < 2; j++) {
        int base = (lane + 32 * j) * 2;
        r1[base]     = __floats2bfloat162_rn(va[j].x * inv1, va[j].y * inv1);
        r1[base + 1] = __floats2bfloat162_rn(va[j].z * inv1, va[j].w * inv1);
        r2[base]     = __floats2bfloat162_rn(vb[j].x * inv2, vb[j].y * inv2);
        r2[base + 1] = __floats2bfloat162_rn(vb[j].z * inv2, vb[j].w * inv2);
    }
    if (lane == 0) g_pos[pair] = dot * inv1 * inv2;
}

// ---------------------------------------------------------------------------
// Epilogue helpers for k_sim
// ---------------------------------------------------------------------------
__device__ __forceinline__ void epi_group(const float* f, int mi, int nj, bool diag,
                                          float (&rs)[4], float (&cs)[8][2],
                                          int wm, int wn, int qrow, int qcol) {
    const int lr0 = wm * 32 + mi * 16 + qrow;
    const int lr1 = lr0 + 8;
    const int lc  = wn * 64 + nj * 8 + qcol;
    float e0 = __expf(2.f * f[0]);
    float e1 = __expf(2.f * f[1]);
    float e2 = __expf(2.f * f[2]);
    float e3 = __expf(2.f * f[3]);
    if (diag) {
        if (lc     == lr0) e0 = 0.f;
        if (lc + 1 == lr0) e1 = 0.f;
        if (lc     == lr1) e2 = 0.f;
        if (lc + 1 == lr1) e3 = 0.f;
    }
    rs[2 * mi]     += e0 + e1;
    rs[2 * mi + 1] += e2 + e3;
    cs[nj][0] += e0 + e2;
    cs[nj][1] += e1 + e3;
}

__device__ __forceinline__ void tile_reduce(int I, int J, bool diag,
                                            float (&rs)[4], float (&cs)[8][2],
                                            int wm, int wn, int lane, int qrow) {
#pragma unroll
    for (int s = 0; s < 4; s++) {
        rs[s] += __shfl_xor_sync(0xffffffffu, rs[s], 1);
        rs[s] += __shfl_xor_sync(0xffffffffu, rs[s], 2);
    }
    if ((lane & 3) == 0) {
        int rbase = I * BT + wm * 32 + qrow;
        atomicAdd(&g_denom[rbase],      rs[0]);
        atomicAdd(&g_denom[rbase + 8],  rs[1]);
        atomicAdd(&g_denom[rbase + 16], rs[2]);
        atomicAdd(&g_denom[rbase + 24], rs[3]);
    }
    if (!diag) {
#pragma unroll
        for (int nj = 0; nj < 8; nj++)
#pragma unroll
            for (int c = 0; c < 2; c++) {
                cs[nj][c] += __shfl_xor_sync(0xffffffffu, cs[nj][c], 4);
                cs[nj][c] += __shfl_xor_sync(0xffffffffu, cs[nj][c], 8);
                cs[nj][c] += __shfl_xor_sync(0xffffffffu, cs[nj][c], 16);
            }
        if (lane < 4) {
            int cbase = J * BT + wn * 64 + lane * 2;
#pragma unroll
            for (int nj = 0; nj < 8; nj++) {
                atomicAdd(&g_denom[cbase + nj * 8],     cs[nj][0]);
                atomicAdd(&g_denom[cbase + nj * 8 + 1], cs[nj][1]);
            }
        }
    }
#pragma unroll
    for (int s = 0; s < 4; s++) rs[s] = 0.f;
#pragma unroll
    for (int nj = 0; nj < 8; nj++) { cs[nj][0] = 0.f; cs[nj][1] = 0.f; }
}

// MMA over one tile into acc, with previous tile's exp epilogue interleaved
// into the HMMA issue bubbles (one 4-value group per k-step).
__device__ __forceinline__ void tile_mma(uint32_t sbA, uint32_t sbB,
                                         float (&acc)[2][8][4], float (&prv)[2][8][4],
                                         bool doPrev, bool prevDiag,
                                         float (&rs)[4], float (&cs)[8][2],
                                         int wm, int wn, int lane) {
    const int lrow = lane & 15;
    const int lsel = lane >> 4;
    const int qrow = lane >> 2;
    const int qcol = (lane & 3) * 2;
#pragma unroll
    for (int mi = 0; mi < 2; mi++)
#pragma unroll
        for (int nj = 0; nj < 8; nj++)
#pragma unroll
            for (int q = 0; q < 4; q++) acc[mi][nj][q] = 0.f;

#pragma unroll
    for (int k16 = 0; k16 < 16; ++k16) {
        const int ch = k16 * 2 + lsel;
        uint32_t a[2][4];
#pragma unroll
        for (int mi = 0; mi < 2; mi++) {
            int r = wm * 32 + mi * 16 + lrow;
            uint32_t ad = sbA + (uint32_t)r * 512u + (uint32_t)(((ch ^ (r & 7)) & 31) << 4);
            ldsm_x4(a[mi][0], a[mi][1], a[mi][2], a[mi][3], ad);
        }
        uint32_t b[4][4];
#pragma unroll
        for (int nb = 0; nb < 4; nb++) {
            int r = wn * 64 + nb * 16 + lrow;
            uint32_t bd = sbB + (uint32_t)r * 512u + (uint32_t)(((ch ^ (r & 7)) & 31) << 4);
            ldsm_x4(b[nb][0], b[nb][1], b[nb][2], b[nb][3], bd);
        }
#pragma unroll
        for (int mi = 0; mi < 2; mi++)
#pragma unroll
            for (int nb = 0; nb < 4; nb++) {
                mma16816(acc[mi][2 * nb + 0], a[mi], b[nb][0], b[nb][2]);
                mma16816(acc[mi][2 * nb + 1], a[mi], b[nb][1], b[nb][3]);
            }
        if (doPrev)
            epi_group(prv[k16 >> 3][k16 & 7], k16 >> 3, k16 & 7, prevDiag,
                      rs, cs, wm, wn, qrow, qcol);
    }
}

// ---------------------------------------------------------------------------
// Kernel 2: symmetric bf16 sim-GEMM + exp sums over triangular tiles;
// epilogue of tile t-1 hidden under MMA of tile t.
// ---------------------------------------------------------------------------
__global__ __launch_bounds__(256, 1) void k_sim_mma() {
    extern __shared__ char smem[];
    const uint32_t sbA  = smem_u32(smem);        // 64 KB
    const uint32_t sbB0 = sbA + 65536;           // 64 KB
    const uint32_t sbB1 = sbB0 + 65536;          // 64 KB

    const int t0 = (int)(((long long)NTILES * blockIdx.x) / gridDim.x);
    const int t1 = (int)(((long long)NTILES * (blockIdx.x + 1)) / gridDim.x);

    const int tid  = threadIdx.x;
    const int lane = tid & 31;
    const int wid  = tid >> 5;
    const int wm   = wid & 3;
    const int wn   = wid >> 2;
    const int qrow = lane >> 2;
    const int qcol = (lane & 3) * 2;

    const uint4* zn4 = (const uint4*)g_znbf;
    int curI = -1;
    bool havePrev = false, prevDiag = false;
    int prevI = 0, prevJ = 0;

    float acc0[2][8][4], acc1[2][8][4];
    float rs[4] = {0.f, 0.f, 0.f, 0.f};
    float cs[8][2];
#pragma unroll
    for (int nj = 0; nj < 8; nj++) { cs[nj][0] = 0.f; cs[nj][1] = 0.f; }

    for (int t = t0; t < t1; ++t) {
        int I, J; decode_tile(t, I, J);
        const uint32_t sbB  = ((t - t0) & 1) ? sbB1 : sbB0;
        const uint32_t sbBn = ((t - t0) & 1) ? sbB0 : sbB1;

        if (I != curI) {
            stage_async(sbA, zn4, I * BT, tid);
            stage_async(sbB, zn4, J * BT, tid);
            CP_COMMIT(); CP_WAIT0();
            __syncthreads();
            curI = I;
        }
        if (t + 1 < t1) {
            int In, Jn; decode_tile(t + 1, In, Jn);
            if (In == curI) { stage_async(sbBn, zn4, Jn * BT, tid); CP_COMMIT(); }
        }

        if (((t - t0) & 1) == 0)
            tile_mma(sbA, sbB, acc0, acc1, havePrev, prevDiag, rs, cs, wm, wn, lane);
        else
            tile_mma(sbA, sbB, acc1, acc0, havePrev, prevDiag, rs, cs, wm, wn, lane);

        if (havePrev)
            tile_reduce(prevI, prevJ, prevDiag, rs, cs, wm, wn, lane, qrow);

        havePrev = true; prevDiag = (I == J); prevI = I; prevJ = J;

        CP_WAIT0();
        __syncthreads();
    }

    // Drain the final tile's epilogue.
    if (havePrev) {
        float (&last)[2][8][4] = ((t1 - t0) & 1) ? acc0 : acc1;
#pragma unroll
        for (int g = 0; g < 16; ++g)
            epi_group(last[g >> 3][g & 7], g >> 3, g & 7, prevDiag,
                      rs, cs, wm, wn, qrow, qcol);
        tile_reduce(prevI, prevJ, prevDiag, rs, cs, wm, wn, lane, qrow);
    }
}

// ---------------------------------------------------------------------------
// Kernel 3: loss = (1/2B) * [sum log(denom_r) - 2 * sum log(pos_i)].
// 8192 threads; last block writes the scalar.
// ---------------------------------------------------------------------------
__global__ void k_loss(float* __restrict__ out) {
    int gtid = blockIdx.x * blockDim.x + threadIdx.x;
    float l = __logf(g_denom[gtid]);
    if (gtid < Bn) l -= 2.f * __logf(g_pos[gtid]);
#pragma unroll
    for (int o = 16; o > 0; o >>= 1) l += __shfl_xor_sync(0xffffffffu, l, o);
    if ((threadIdx.x & 31) == 0) atomicAdd(&g_loss, l);
    __syncthreads();
    if (threadIdx.x == 0) {
        __threadfence();
        unsigned int done = atomicAdd(&g_count, 1u);
        if (done == gridDim.x - 1)
            out[0] = g_loss * (1.f / (float)TWOB);
    }
}

// ---------------------------------------------------------------------------
extern "C" void kernel_launch(void* const* d_in, const int* in_sizes, int n_in,
                              void* d_out, int out_size) {
    const float* z1 = (const float*)d_in[0];
    const float* z2 = (const float*)d_in[1];
    float* out = (float*)d_out;

    int nsm = 148;
    cudaDeviceGetAttribute(&nsm, cudaDevAttrMultiProcessorCount, 0);

    const int smem_bytes = 3 * 65536;   // 192 KB
    cudaFuncSetAttribute(k_sim_mma, cudaFuncAttributeMaxDynamicSharedMemorySize, smem_bytes);

    k_prep<<<Bn * 32 / 256, 256>>>(z1, z2);
    k_sim_mma<<<nsm, 256, smem_bytes>>>();
    k_loss<<<TWOB / 256, 256>>>(out);
}

// round 6
// speedup vs baseline: 15.0068x; 1.2068x over previous
#include <cuda_runtime.h>
#include <cuda_bf16.h>
#include <cstdint>

#define Bn    4096
#define TWOB  8192
#define D     256
#define BT    128               // tile edge
#define NT    (TWOB / BT)       // 64 tile bands
#define NTILES (NT * (NT + 1) / 2)   // 2080 triangular tiles

// Scratch (device globals — no allocation allowed)
__device__ __align__(16) uint8_t g_znq[TWOB * D];   // e4m3 normalized (GEMM operand)
__device__ float g_pos[Bn];      // exact fp32 positive cosine sims
__device__ float g_denom[TWOB];
__device__ float g_loss;
__device__ unsigned int g_count;

// ---------------------------------------------------------------------------
__device__ __forceinline__ uint32_t smem_u32(const void* p) {
    uint32_t a;
    asm("{ .reg .u64 t; cvta.to.shared.u64 t, %1; cvt.u32.u64 %0, t; }" : "=r"(a) : "l"(p));
    return a;
}
__device__ __forceinline__ void ldsm_x4(uint32_t& r0, uint32_t& r1, uint32_t& r2, uint32_t& r3,
                                        uint32_t addr) {
    asm volatile("ldmatrix.sync.aligned.m8n8.x4.shared.b16 {%0,%1,%2,%3}, [%4];"
                 : "=r"(r0), "=r"(r1), "=r"(r2), "=r"(r3) : "r"(addr));
}
// FP8 e4m3 MMA, m16n8k32 (baseline PTX, sm_89+)
__device__ __forceinline__ void mma_fp8(float* c, const uint32_t* a, uint32_t b0, uint32_t b1) {
    asm volatile(
        "mma.sync.aligned.m16n8k32.row.col.f32.e4m3.e4m3.f32 "
        "{%0,%1,%2,%3}, {%4,%5,%6,%7}, {%8,%9}, {%0,%1,%2,%3};"
        : "+f"(c[0]), "+f"(c[1]), "+f"(c[2]), "+f"(c[3])
        : "r"(a[0]), "r"(a[1]), "r"(a[2]), "r"(a[3]), "r"(b0), "r"(b1));
}
// pack two fp32 -> e4m3x2 (byte0 = v0, byte1 = v1)
__device__ __forceinline__ uint16_t pack_e4m3(float v0, float v1) {
    uint16_t r;
    asm("cvt.rn.satfinite.e4m3x2.f32 %0, %1, %2;" : "=h"(r) : "f"(v1), "f"(v0));
    return r;
}
#define CP_COMMIT() asm volatile("cp.async.commit_group;" ::: "memory")
#define CP_WAIT0()  asm volatile("cp.async.wait_group 0;" ::: "memory")

// Async-stage one 128x256B fp8 tile. Row r (256 B = 16 chunks of 16 B);
// chunk c stored at r*256 + ((c ^ (r&7)) << 4).
__device__ __forceinline__ void stage_async(uint32_t sbase, const uint8_t* __restrict__ src,
                                            int row0, int tid) {
#pragma unroll
    for (int it = 0; it < 8; ++it) {
        int i = it * 256 + tid;
        int r = i >> 4, c = i & 15;
        const uint8_t* g = src + (size_t)(row0 + r) * 256 + c * 16;
        uint32_t dst = sbase + (uint32_t)r * 256u + (uint32_t)((c ^ (r & 7)) << 4);
        asm volatile("cp.async.cg.shared.global [%0], [%1], 16;" :: "r"(dst), "l"(g));
    }
}

__device__ __forceinline__ void decode_tile(int t, int& I, int& J) {
    int i = 0, s = 0;
    while (s + (NT - i) <= t) { s += NT - i; ++i; }
    I = i; J = i + (t - s);
}

// ldmatrix address for a 16-row x 32-byte (k32) fragment group at rows m0..+15,
// byte-chunk pair starting at chunk 2*kc. Lane L supplies matrix (L>>3)'s row (L&7).
__device__ __forceinline__ uint32_t frag_addr(uint32_t sbase, int m0, int kc, int lane) {
    int m  = lane >> 3;           // matrix 0..3
    int r  = m0 + (lane & 7) + ((m & 1) << 3);
    int ch = 2 * kc + (m >> 1);
    return sbase + (uint32_t)r * 256u + (uint32_t)(((ch ^ (r & 7)) & 15) << 4);
}

// ---------------------------------------------------------------------------
// Kernel 1: normalize row pairs (z1_i, z2_i); emit e4m3 rows i and i+Bn,
// exact fp32 positive sims; zero accumulators. One warp per pair, float4 IO.
// ---------------------------------------------------------------------------
__global__ void k_prep(const float* __restrict__ z1, const float* __restrict__ z2) {
    int gtid = blockIdx.x * blockDim.x + threadIdx.x;
    if (gtid < TWOB) g_denom[gtid] = 0.f;
    if (gtid == 0)   { g_loss = 0.f; g_count = 0u; }
    int pair = gtid >> 5;
    int lane = gtid & 31;
    if (pair >= Bn) return;
    const float4* a4 = (const float4*)(z1 + (size_t)pair * D);
    const float4* b4 = (const float4*)(z2 + (size_t)pair * D);
    float4 va[2], vb[2];
    float ss1 = 0.f, ss2 = 0.f, dot = 0.f;
#pragma unroll
    for (int j = 0; j < 2; j++) {
        va[j] = a4[lane + 32 * j];
        vb[j] = b4[lane + 32 * j];
        ss1 += va[j].x * va[j].x + va[j].y * va[j].y + va[j].z * va[j].z + va[j].w * va[j].w;
        ss2 += vb[j].x * vb[j].x + vb[j].y * vb[j].y + vb[j].z * vb[j].z + vb[j].w * vb[j].w;
        dot += va[j].x * vb[j].x + va[j].y * vb[j].y + va[j].z * vb[j].z + va[j].w * vb[j].w;
    }
#pragma unroll
    for (int o = 16; o > 0; o >>= 1) {
        ss1 += __shfl_xor_sync(0xffffffffu, ss1, o);
        ss2 += __shfl_xor_sync(0xffffffffu, ss2, o);
        dot += __shfl_xor_sync(0xffffffffu, dot, o);
    }
    float inv1 = 1.f / fmaxf(sqrtf(ss1), 1e-8f);
    float inv2 = 1.f / fmaxf(sqrtf(ss2), 1e-8f);

    uint32_t* r1 = (uint32_t*)(g_znq + (size_t)pair * D);
    uint32_t* r2 = (uint32_t*)(g_znq + (size_t)(pair + Bn) * D);
#pragma unroll
    for (int j = 0; j < 2; j++) {
        uint32_t w1 = (uint32_t)pack_e4m3(va[j].x * inv1, va[j].y * inv1)
                    | ((uint32_t)pack_e4m3(va[j].z * inv1, va[j].w * inv1) << 16);
        uint32_t w2 = (uint32_t)pack_e4m3(vb[j].x * inv2, vb[j].y * inv2)
                    | ((uint32_t)pack_e4m3(vb[j].z * inv2, vb[j].w * inv2) << 16);
        r1[lane + 32 * j] = w1;
        r2[lane + 32 * j] = w2;
    }
    if (lane == 0) g_pos[pair] = dot * inv1 * inv2;
}

// ---------------------------------------------------------------------------
// Kernel 2: symmetric e4m3 sim-GEMM + exp sums over triangular tiles.
// 2 CTAs/SM (96 KB smem, <=128 regs); cross-CTA overlap hides epilogue.
// 8 warps: 4 along M x 2 along N; warp tile 32x64; K=256 in 8 k32 steps.
// ---------------------------------------------------------------------------
__global__ __launch_bounds__(256, 2) void k_sim_mma() {
    extern __shared__ char smem[];
    const uint32_t sbA  = smem_u32(smem);        // 32 KB
    const uint32_t sbB0 = sbA + 32768;           // 32 KB
    const uint32_t sbB1 = sbB0 + 32768;          // 32 KB

    const int t0 = (int)(((long long)NTILES * blockIdx.x) / gridDim.x);
    const int t1 = (int)(((long long)NTILES * (blockIdx.x + 1)) / gridDim.x);

    const int tid  = threadIdx.x;
    const int lane = tid & 31;
    const int wid  = tid >> 5;
    const int wm   = wid & 3;       // 4 warps along M (32 rows each)
    const int wn   = wid >> 2;      // 2 warps along N (64 cols each)
    const int qrow = lane >> 2;
    const int qcol = (lane & 3) * 2;

    int curI = -1;

    for (int t = t0; t < t1; ++t) {
        int I, J; decode_tile(t, I, J);
        const uint32_t sbB  = ((t - t0) & 1) ? sbB1 : sbB0;
        const uint32_t sbBn = ((t - t0) & 1) ? sbB0 : sbB1;

        if (I != curI) {
            stage_async(sbA, g_znq, I * BT, tid);
            stage_async(sbB, g_znq, J * BT, tid);
            CP_COMMIT(); CP_WAIT0();
            __syncthreads();
            curI = I;
        }
        if (t + 1 < t1) {
            int In, Jn; decode_tile(t + 1, In, Jn);
            if (In == curI) { stage_async(sbBn, g_znq, Jn * BT, tid); CP_COMMIT(); }
        }

        // ---- compute 128x128 tile: 8 k32 steps ----
        float acc[2][8][4];
#pragma unroll
        for (int mi = 0; mi < 2; mi++)
#pragma unroll
            for (int nj = 0; nj < 8; nj++)
#pragma unroll
                for (int q = 0; q < 4; q++) acc[mi][nj][q] = 0.f;

#pragma unroll
        for (int kc = 0; kc < 8; ++kc) {
            uint32_t a[2][4];
#pragma unroll
            for (int mi = 0; mi < 2; mi++)
                ldsm_x4(a[mi][0], a[mi][1], a[mi][2], a[mi][3],
                        frag_addr(sbA, wm * 32 + mi * 16, kc, lane));
            uint32_t b[4][4];
#pragma unroll
            for (int nb = 0; nb < 4; nb++)
                ldsm_x4(b[nb][0], b[nb][1], b[nb][2], b[nb][3],
                        frag_addr(sbB, wn * 64 + nb * 16, kc, lane));
#pragma unroll
            for (int mi = 0; mi < 2; mi++)
#pragma unroll
                for (int nb = 0; nb < 4; nb++) {
                    mma_fp8(acc[mi][2 * nb + 0], a[mi], b[nb][0], b[nb][2]);
                    mma_fp8(acc[mi][2 * nb + 1], a[mi], b[nb][1], b[nb][3]);
                }
        }

        // ---- epilogue: exp(2*sim); row sums always, col sums if I != J ----
        const bool diag = (I == J);
        float rs[4] = {0.f, 0.f, 0.f, 0.f};
        float cs[8][2];
#pragma unroll
        for (int nj = 0; nj < 8; nj++) { cs[nj][0] = 0.f; cs[nj][1] = 0.f; }

#pragma unroll
        for (int mi = 0; mi < 2; mi++) {
            const int lr0 = wm * 32 + mi * 16 + qrow;
            const int lr1 = lr0 + 8;
#pragma unroll
            for (int nj = 0; nj < 8; nj++) {
                const int lc = wn * 64 + nj * 8 + qcol;
                const float* f = acc[mi][nj];
                float e0 = __expf(2.f * f[0]);
                float e1 = __expf(2.f * f[1]);
                float e2 = __expf(2.f * f[2]);
                float e3 = __expf(2.f * f[3]);
                if (diag) {
                    if (lc     == lr0) e0 = 0.f;
                    if (lc + 1 == lr0) e1 = 0.f;
                    if (lc     == lr1) e2 = 0.f;
                    if (lc + 1 == lr1) e3 = 0.f;
                }
                rs[2 * mi]     += e0 + e1;
                rs[2 * mi + 1] += e2 + e3;
                cs[nj][0] += e0 + e2;
                cs[nj][1] += e1 + e3;
            }
        }

#pragma unroll
        for (int s = 0; s < 4; s++) {
            rs[s] += __shfl_xor_sync(0xffffffffu, rs[s], 1);
            rs[s] += __shfl_xor_sync(0xffffffffu, rs[s], 2);
        }
        if ((lane & 3) == 0) {
            int rbase = I * BT + wm * 32 + qrow;
            atomicAdd(&g_denom[rbase],      rs[0]);
            atomicAdd(&g_denom[rbase + 8],  rs[1]);
            atomicAdd(&g_denom[rbase + 16], rs[2]);
            atomicAdd(&g_denom[rbase + 24], rs[3]);
        }
        if (!diag) {
#pragma unroll
            for (int nj = 0; nj < 8; nj++)
#pragma unroll
                for (int c = 0; c < 2; c++) {
                    cs[nj][c] += __shfl_xor_sync(0xffffffffu, cs[nj][c], 4);
                    cs[nj][c] += __shfl_xor_sync(0xffffffffu, cs[nj][c], 8);
                    cs[nj][c] += __shfl_xor_sync(0xffffffffu, cs[nj][c], 16);
                }
            if (lane < 4) {
                int cbase = J * BT + wn * 64 + lane * 2;
#pragma unroll
                for (int nj = 0; nj < 8; nj++) {
                    atomicAdd(&g_denom[cbase + nj * 8],     cs[nj][0]);
                    atomicAdd(&g_denom[cbase + nj * 8 + 1], cs[nj][1]);
                }
            }
        }

        CP_WAIT0();        // next B landed
        __syncthreads();
    }
}

// ---------------------------------------------------------------------------
// Kernel 3: loss = (1/2B) * [sum log(denom_r) - 2 * sum log(pos_i)].
// ---------------------------------------------------------------------------
__global__ void k_loss(float* __restrict__ out) {
    int gtid = blockIdx.x * blockDim.x + threadIdx.x;
    float l = __logf(g_denom[gtid]);
    if (gtid < Bn) l -= 2.f * __logf(g_pos[gtid]);
#pragma unroll
    for (int o = 16; o > 0; o >>= 1) l += __shfl_xor_sync(0xffffffffu, l, o);
    if ((threadIdx.x & 31) == 0) atomicAdd(&g_loss, l);
    __syncthreads();
    if (threadIdx.x == 0) {
        __threadfence();
        unsigned int done = atomicAdd(&g_count, 1u);
        if (done == gridDim.x - 1)
            out[0] = g_loss * (1.f / (float)TWOB);
    }
}

// ---------------------------------------------------------------------------
extern "C" void kernel_launch(void* const* d_in, const int* in_sizes, int n_in,
                              void* d_out, int out_size) {
    const float* z1 = (const float*)d_in[0];
    const float* z2 = (const float*)d_in[1];
    float* out = (float*)d_out;

    int nsm = 148;
    cudaDeviceGetAttribute(&nsm, cudaDevAttrMultiProcessorCount, 0);

    const int smem_bytes = 3 * 32768;   // 96 KB
    cudaFuncSetAttribute(k_sim_mma, cudaFuncAttributeMaxDynamicSharedMemorySize, smem_bytes);

    k_prep<<<Bn * 32 / 256, 256>>>(z1, z2);
    k_sim_mma<<<2 * nsm, 256, smem_bytes>>>();
    k_loss<<<TWOB / 256, 256>>>(out);
}